// round 7
// baseline (speedup 1.0000x reference)
#include <cuda_runtime.h>

#define N_NODES 10000
#define N_EDGES 160000
#define C       16
#define C2      8
#define HID     64
#define NH      2
#define NG      16
#define F_IN    64
#define F_OUT   32
#define NI      65

#define GRID    290
#define NTHR    (GRID * 256)          // 74240
#define EPT     3                     // max edges per thread
#define NODE_BLK_LIM 79               // blocks carrying (n,h) pair work (79*256=20224>=20000)
#define NPAIR   (N_NODES * NH)        // 20000

// ---------------- scratch (device globals; no allocations allowed) ----------
__device__ __align__(16) float g_x[N_NODES * C];
__device__ __align__(16) float g_q[N_NODES * NH * C];
__device__ __align__(16) float g_k[N_NODES * NH * C];
__device__ __align__(16) float g_u[N_NODES * NH * 16];   // [n][h][u0(8),u1(8)]
__device__ __align__(8) unsigned g_m[N_NODES * NH];
__device__ __align__(8) float    g_z[N_NODES * NH];
__device__ __align__(16) float g_accp[N_NODES * NH * C2];
__device__ float    g_pooled[NG * NH * C2];
__device__ int      g_barcnt;        // global barrier counter (reset at end of each launch)
__device__ int      g_fast;

// piecewise-linear tables
__device__ float g_t [NH][HID];
__device__ __align__(16) float g_S0[NH][NI][C];
__device__ __align__(16) float g_S1[NH][NI][C];
__device__ float g_A0[NH][NI];
__device__ float g_A1[NH][NI];

__device__ __forceinline__ unsigned fenc(float f) {
    unsigned u = __float_as_uint(f);
    return (u & 0x80000000u) ? ~u : (u | 0x80000000u);
}
__device__ __forceinline__ float fdec(unsigned u) {
    return (u & 0x80000000u) ? __uint_as_float(u & 0x7fffffffu)
                             : __uint_as_float(~u);
}
#define ENC_NEG_INF 0x007FFFFFu

__device__ __forceinline__ void red_v4(float* p, float4 v) {
    asm volatile("red.global.add.v4.f32 [%0], {%1, %2, %3, %4};"
                 :: "l"(p), "f"(v.x), "f"(v.y), "f"(v.z), "f"(v.w) : "memory");
}
__device__ __forceinline__ void red_f(float* p, float v) {
    asm volatile("red.global.add.f32 [%0], %1;" :: "l"(p), "f"(v) : "memory");
}
__device__ __forceinline__ int ld_acq(const int* p) {
    int v; asm volatile("ld.global.acquire.gpu.b32 %0, [%1];" : "=r"(v) : "l"(p) : "memory");
    return v;
}

// software grid barrier: release-arrive + acquire-spin + L1 invalidate
__device__ __forceinline__ void gbar(int target) {
    __syncthreads();
    if (threadIdx.x == 0) {
        __threadfence();
        atomicAdd(&g_barcnt, 1);
        while (ld_acq(&g_barcnt) < target) __nanosleep(64);
        __threadfence();   // fence.gpu -> CCTL.IVALL: invalidate this SM's L1
    }
    __syncthreads();
}

__device__ __forceinline__ int bsearch64g(const float* t, float df) {
    int lo = 0, hi = HID;
#pragma unroll
    for (int it = 0; it < 7; it++) {
        if (lo < hi) {
            int mid = (lo + hi) >> 1;
            if (__ldcg(t + mid) < df) lo = mid + 1; else hi = mid;
        }
    }
    return lo;
}

// ---------------- the single fused persistent kernel ------------------------
__global__ void __launch_bounds__(256, 2)
k_fused(const float* __restrict__ NF,  const float* __restrict__ pos,
        const float* __restrict__ We,  const float* __restrict__ be,
        const float* __restrict__ Wq,  const float* __restrict__ Wk,
        const float* __restrict__ W1,  const float* __restrict__ b1,
        const float* __restrict__ Wa,  const float* __restrict__ Wv,
        const float* __restrict__ Wo,  const float* __restrict__ Wproj,
        const float* __restrict__ bproj,
        const int* __restrict__ ei,    const int* __restrict__ batch,
        float* __restrict__ out) {
    int tid  = threadIdx.x;
    int gtid = blockIdx.x * 256 + tid;

    __shared__ float sWe[F_IN * C];
    __shared__ float sbe[C];
    __shared__ float sWq[NH * C * C];
    __shared__ float sWk[NH * C * C];
    __shared__ float sraw[NH * HID];
    __shared__ float sstt[NH * HID];
    __shared__ int   s_last;

    // ================= PHASE 0: tables (block 0) + node embed/q/k/init ======
    if (blockIdx.x == 0) {
        if (tid < NH * HID) {
            int h = tid / HID, j = tid % HID;
            float w = W1[h * HID + j], b = b1[h * HID + j];
            sraw[tid] = (w != 0.f) ? (-b / w) : -1e30f;
        }
        __syncthreads();
        if (tid < NH * HID) {
            int h = tid / HID, j = tid % HID;
            float v = sraw[tid];
            int rank = 0;
            for (int i = 0; i < HID; i++) {
                float o = sraw[h * HID + i];
                rank += (o < v || (o == v && i < j)) ? 1 : 0;
            }
            sstt[h * HID + rank] = v;
            g_t[h][rank] = v;
        }
        __syncthreads();
        if (tid == 0) {
            int npos = 0;
            for (int i = 0; i < NH * HID; i++) npos += (sstt[i] > 0.f) ? 1 : 0;
            g_fast = (npos == 0) ? 1 : 0;
        }
        if (tid < NH * NI) {
            int h = tid / NI, i = tid % NI;
            float lo = (i == 0)   ? sstt[h * HID + 0] - 1.0f        : sstt[h * HID + i - 1];
            float hi = (i == HID) ? sstt[h * HID + HID - 1] + 1.0f  : sstt[h * HID + i];
            float mid = 0.5f * (lo + hi);
            float S0[C], S1[C], A0 = 0.f, A1 = 0.f;
#pragma unroll
            for (int c = 0; c < C; c++) { S0[c] = 0.f; S1[c] = 0.f; }
            for (int j = 0; j < HID; j++) {
                float w = W1[h * HID + j], b = b1[h * HID + j];
                if (fmaf(w, mid, b) > 0.f) {
                    float wa = Wa[h * HID + j];
                    A0 = fmaf(b, wa, A0);
                    A1 = fmaf(w, wa, A1);
#pragma unroll
                    for (int c = 0; c < C; c++) {
                        float wv = Wv[(h * HID + j) * (C * 3) + 3 * c];
                        S0[c] = fmaf(b, wv, S0[c]);
                        S1[c] = fmaf(w, wv, S1[c]);
                    }
                }
            }
#pragma unroll
            for (int c = 0; c < C; c++) { g_S0[h][i][c] = S0[c]; g_S1[h][i][c] = S1[c]; }
            g_A0[h][i] = A0; g_A1[h][i] = A1;
        }
        if (tid < NG * NH * C2) g_pooled[tid] = 0.f;
        __syncthreads();
    }

    if (blockIdx.x < NODE_BLK_LIM) {
        for (int i = tid; i < F_IN * C; i += 256) sWe[i] = We[i];
        for (int i = tid; i < C; i += 256) sbe[i] = be[i];
        for (int i = tid; i < NH * C * C; i += 256) { sWq[i] = Wq[i]; sWk[i] = Wk[i]; }
        __syncthreads();

        if (gtid < NPAIR) {
            int n = gtid >> 1;
            int h = gtid & 1;
            if (h == 0) {
                *(uint2*)(g_m + n * NH) = make_uint2(ENC_NEG_INF, ENC_NEG_INF);
                *(float2*)(g_z + n * NH) = make_float2(0.f, 0.f);
                float4 zf4 = make_float4(0.f, 0.f, 0.f, 0.f);
                float4* ac = (float4*)(g_accp + n * NH * C2);
#pragma unroll
                for (int i = 0; i < 4; i++) ac[i] = zf4;
            }
            float x[C];
#pragma unroll
            for (int j = 0; j < C; j++) x[j] = sbe[j];
            const float4* nf4 = (const float4*)(NF + n * F_IN);
#pragma unroll
            for (int i4 = 0; i4 < F_IN / 4; i4++) {
                float4 v = nf4[i4];
                float vs[4] = { v.x, v.y, v.z, v.w };
#pragma unroll
                for (int k = 0; k < 4; k++) {
                    float vv = vs[k];
                    int i = i4 * 4 + k;
#pragma unroll
                    for (int j = 0; j < C; j++) x[j] = fmaf(vv, sWe[i * C + j], x[j]);
                }
            }
            if (h == 0) {
#pragma unroll
                for (int j = 0; j < C; j++) g_x[n * C + j] = x[j];
            }
            float q[C], k[C];
#pragma unroll
            for (int j = 0; j < C; j++) { q[j] = 0.f; k[j] = 0.f; }
#pragma unroll
            for (int i = 0; i < C; i++) {
                float xi = x[i];
#pragma unroll
                for (int j = 0; j < C; j++) {
                    q[j] = fmaf(xi, sWq[h * C * C + i * C + j], q[j]);
                    k[j] = fmaf(xi, sWk[h * C * C + i * C + j], k[j]);
                }
            }
            float* qp = g_q + (n * NH + h) * C;
            float* kp = g_k + (n * NH + h) * C;
#pragma unroll
            for (int j = 0; j < C; j++) { qp[j] = q[j]; kp[j] = k[j]; }
        }
    }

    gbar(GRID);

    // ================= PHASE 1: u-vectors + edge logits + segment max =======
    int fast = __ldcg(&g_fast);

    if (fast && gtid < NPAIR) {
        int n = gtid >> 1;
        int h = gtid & 1;
        float x[C];
        {
            const float4* xp = (const float4*)(g_x + n * C);
#pragma unroll
            for (int i4 = 0; i4 < 4; i4++) {
                float4 v = __ldcg(xp + i4);
                x[i4 * 4 + 0] = v.x; x[i4 * 4 + 1] = v.y;
                x[i4 * 4 + 2] = v.z; x[i4 * 4 + 3] = v.w;
            }
        }
        float u0[C2], u1[C2];
#pragma unroll
        for (int j = 0; j < C2; j++) { u0[j] = 0.f; u1[j] = 0.f; }
#pragma unroll
        for (int c = 0; c < C; c++) {
            float xc = x[c];
            float s0 = __ldcg(&g_S0[h][HID][c]) * xc;
            float s1 = __ldcg(&g_S1[h][HID][c]) * xc;
            const float* wo = Wo + h * 3 * C * C2 + c * C2;   // li=0 slice
#pragma unroll
            for (int j = 0; j < C2; j++) {
                u0[j] = fmaf(s0, wo[j], u0[j]);
                u1[j] = fmaf(s1, wo[j], u1[j]);
            }
        }
        float4* up = (float4*)(g_u + (n * NH + h) * 16);
        up[0] = make_float4(u0[0], u0[1], u0[2], u0[3]);
        up[1] = make_float4(u0[4], u0[5], u0[6], u0[7]);
        up[2] = make_float4(u1[0], u1[1], u1[2], u1[3]);
        up[3] = make_float4(u1[4], u1[5], u1[6], u1[7]);
    }

    float fA0[NH], fA1[NH];
    if (fast) {
#pragma unroll
        for (int h = 0; h < NH; h++) { fA0[h] = __ldcg(&g_A0[h][HID]); fA1[h] = __ldcg(&g_A1[h][HID]); }
    }

    int   es[EPT], et[EPT];
    float ed[EPT], el0[EPT], el1[EPT];
#pragma unroll
    for (int kk = 0; kk < EPT; kk++) {
        int e = gtid + kk * NTHR;
        if (e < N_EDGES) {
            int s = ei[e];
            int t = ei[N_EDGES + e];
            es[kk] = s; et[kk] = t;
            float dx = pos[3 * t + 0] - pos[3 * s + 0];
            float dy = pos[3 * t + 1] - pos[3 * s + 1];
            float dz = pos[3 * t + 2] - pos[3 * s + 2];
            float d2 = dx * dx + dy * dy + dz * dz;
            float d  = sqrtf(d2);
            ed[kk] = d;
            float df_h[NH] = { d, 1.0f / d2 };
#pragma unroll
            for (int h = 0; h < NH; h++) {
                float df = df_h[h];
                float ab;
                if (fast) {
                    ab = fmaf(df, fA1[h], fA0[h]);
                } else {
                    int idx = bsearch64g(&g_t[h][0], df);
                    ab = fmaf(df, __ldcg(&g_A1[h][idx]), __ldcg(&g_A0[h][idx]));
                }
                const float4* qt = (const float4*)(g_q + (t * NH + h) * C);
                const float4* ks = (const float4*)(g_k + (s * NH + h) * C);
                float dot = 0.f;
#pragma unroll
                for (int i4 = 0; i4 < 4; i4++) {
                    float4 a = qt[i4], b = ks[i4];
                    dot += a.x * b.x + a.y * b.y + a.z * b.z + a.w * b.w;
                }
                float lg = fmaf(dot, 0.25f, ab);
                if (h == 0) el0[kk] = lg; else el1[kk] = lg;
                atomicMax(&g_m[t * NH + h], fenc(lg));
            }
        }
    }

    gbar(2 * GRID);

    // ================= PHASE 2: exp + message accumulate =====================
#pragma unroll
    for (int kk = 0; kk < EPT; kk++) {
        int e = gtid + kk * NTHR;
        if (e < N_EDGES) {
            int s = es[kk], t = et[kk];
            float d = ed[kk];
            float df_h[NH] = { d, 1.0f / (d * d) };
            uint2 m2 = __ldcg((const uint2*)(g_m + t * NH));
            float lg_h[NH] = { el0[kk], el1[kk] };
            float m_h [NH] = { fdec(m2.x), fdec(m2.y) };

            if (fast) {
                const float4* up = (const float4*)(g_u + s * NH * 16);
#pragma unroll
                for (int h = 0; h < NH; h++) {
                    float ex = __expf(lg_h[h] - m_h[h]);
                    red_f(&g_z[t * NH + h], ex);
                    float df = df_h[h];
                    float4 u0l = __ldcg(up + h * 4 + 0), u0h = __ldcg(up + h * 4 + 1);
                    float4 u1l = __ldcg(up + h * 4 + 2), u1h = __ldcg(up + h * 4 + 3);
                    float4 plo, phi;
                    plo.x = ex * fmaf(df, u1l.x, u0l.x);
                    plo.y = ex * fmaf(df, u1l.y, u0l.y);
                    plo.z = ex * fmaf(df, u1l.z, u0l.z);
                    plo.w = ex * fmaf(df, u1l.w, u0l.w);
                    phi.x = ex * fmaf(df, u1h.x, u0h.x);
                    phi.y = ex * fmaf(df, u1h.y, u0h.y);
                    phi.z = ex * fmaf(df, u1h.z, u0h.z);
                    phi.w = ex * fmaf(df, u1h.w, u0h.w);
                    float* accp = g_accp + (t * NH + h) * C2;
                    red_v4(accp,     plo);
                    red_v4(accp + 4, phi);
                }
            } else {
                float xs[C];
                const float4* xp = (const float4*)(g_x + s * C);
#pragma unroll
                for (int i4 = 0; i4 < 4; i4++) {
                    float4 v = __ldcg(xp + i4);
                    xs[i4 * 4 + 0] = v.x; xs[i4 * 4 + 1] = v.y;
                    xs[i4 * 4 + 2] = v.z; xs[i4 * 4 + 3] = v.w;
                }
#pragma unroll
                for (int h = 0; h < NH; h++) {
                    float ex = __expf(lg_h[h] - m_h[h]);
                    red_f(&g_z[t * NH + h], ex);
                    float df = df_h[h];
                    int idx = bsearch64g(&g_t[h][0], df);
                    float p[C2];
#pragma unroll
                    for (int j = 0; j < C2; j++) p[j] = 0.f;
#pragma unroll
                    for (int c = 0; c < C; c++) {
                        float w = fmaf(df, __ldcg(&g_S1[h][idx][c]), __ldcg(&g_S0[h][idx][c])) * xs[c];
                        const float* wo = Wo + h * 3 * C * C2 + c * C2;
#pragma unroll
                        for (int j = 0; j < C2; j++) p[j] = fmaf(w, wo[j], p[j]);
                    }
                    float* accp = g_accp + (t * NH + h) * C2;
                    red_v4(accp,     make_float4(ex * p[0], ex * p[1], ex * p[2], ex * p[3]));
                    red_v4(accp + 4, make_float4(ex * p[4], ex * p[5], ex * p[6], ex * p[7]));
                }
            }
        }
    }

    gbar(3 * GRID);

    // ================= PHASE 3: normalize + pool =============================
    {
        int lane = tid & 31;
        float v[C2];
#pragma unroll
        for (int j = 0; j < C2; j++) v[j] = 0.f;
        int g = 0;
        bool valid = (gtid < NPAIR);
        int n = gtid >> 1;
        int h = gtid & 1;
        if (valid) {
            g = batch[n];
            float z = __ldcg(&g_z[n * NH + h]);
            if (z > 0.f) {
                float inv = 1.0f / z;
                const float4* ap = (const float4*)(g_accp + (n * NH + h) * C2);
                float4 a0 = __ldcg(ap), a1 = __ldcg(ap + 1);
                v[0] = a0.x * inv; v[1] = a0.y * inv; v[2] = a0.z * inv; v[3] = a0.w * inv;
                v[4] = a1.x * inv; v[5] = a1.y * inv; v[6] = a1.z * inv; v[7] = a1.w * inv;
            }
        }
        int g0 = __shfl_sync(0xffffffffu, g, 0);
        bool uniform = __all_sync(0xffffffffu, valid && (g == g0));
        if (uniform) {
#pragma unroll
            for (int j = 0; j < C2; j++) {
#pragma unroll
                for (int ofs = 16; ofs >= 2; ofs >>= 1)
                    v[j] += __shfl_xor_sync(0xffffffffu, v[j], ofs);
            }
            if (lane < 2) {
                float* dst = g_pooled + (g0 * NH + h) * C2;
                red_v4(dst,     make_float4(v[0], v[1], v[2], v[3]));
                red_v4(dst + 4, make_float4(v[4], v[5], v[6], v[7]));
            }
        } else if (valid) {
            float* dst = g_pooled + (g * NH + h) * C2;
#pragma unroll
            for (int jj = 0; jj < C2; jj++) {
                int j = (jj + lane) & (C2 - 1);
                red_f(dst + j, v[j]);
            }
        }
    }

    // ================= FINAL: last-arriver does projection + counter reset ===
    __syncthreads();
    if (tid == 0) {
        __threadfence();
        int old = atomicAdd(&g_barcnt, 1);
        s_last = (old == 4 * GRID - 1) ? 1 : 0;
    }
    __syncthreads();
    if (s_last) {
        if (tid == 0) __threadfence();   // acquire side: invalidate L1
        __syncthreads();
#pragma unroll
        for (int r = 0; r < 2; r++) {
            int idx = tid + r * 256;
            int gg = idx / F_OUT;
            int oo = idx % F_OUT;
            float acc = bproj[oo];
#pragma unroll
            for (int t2 = 0; t2 < NH * C2; t2++)
                acc = fmaf(__ldcg(&g_pooled[gg * (NH * C2) + t2]), Wproj[t2 * F_OUT + oo], acc);
            out[gg * F_OUT + oo] = acc;
        }
        __syncthreads();
        if (tid == 0) {
            __threadfence();
            *((volatile int*)&g_barcnt) = 0;   // reset for next replay
        }
    }
}

// ---------------- launch ----------------------------------------------------
extern "C" void kernel_launch(void* const* d_in, const int* in_sizes, int n_in,
                              void* d_out, int out_size) {
    const float* NF    = (const float*)d_in[0];
    const float* pos   = (const float*)d_in[1];
    const float* We    = (const float*)d_in[2];
    const float* be    = (const float*)d_in[3];
    const float* Wq    = (const float*)d_in[4];
    const float* Wk    = (const float*)d_in[5];
    const float* W1    = (const float*)d_in[6];
    const float* b1    = (const float*)d_in[7];
    const float* Wa    = (const float*)d_in[8];
    const float* Wv    = (const float*)d_in[9];
    const float* Wo    = (const float*)d_in[10];
    const float* Wproj = (const float*)d_in[11];
    const float* bproj = (const float*)d_in[12];
    const int*   ei    = (const int*)d_in[13];
    const int*   batch = (const int*)d_in[14];
    float* out = (float*)d_out;

    k_fused<<<GRID, 256>>>(NF, pos, We, be, Wq, Wk, W1, b1, Wa, Wv, Wo,
                           Wproj, bproj, ei, batch, out);
}